// round 2
// baseline (speedup 1.0000x reference)
#include <cuda_runtime.h>

#define IN_DIM   2048
#define OUT_DIM  14951
#define THREADS  256
#define R        4
#define EPS      1e-12f

__global__ __launch_bounds__(THREADS)
void hc_kernel(const float* __restrict__ x,
               const float* __restrict__ scale,
               const float* __restrict__ bias,
               float* __restrict__ out,
               int rowstride)   // = batch / R
{
    __shared__ float xch[8][THREADS];      // 8 KB exchange buffer (conflict-free)
    __shared__ float sred[THREADS / 32];
    __shared__ float sc[R];

    const int t    = threadIdx.x;
    const int b    = blockIdx.x;
    const int lane = t & 31;

    // res[k][q] holds element n = q*256 + t of row k's (partial) transform
    float res[R][8];

    const float scl = scale[0];

    #pragma unroll
    for (int k = 0; k < R; ++k) {
        const float* __restrict__ xr = x + (size_t)(b + k * rowstride) * IN_DIM;

        // ---- load (coalesced scalar) + sum of squares ----
        float ss = 0.f;
        #pragma unroll
        for (int q = 0; q < 8; ++q) {
            float v = xr[q * THREADS + t];
            res[k][q] = v;
            ss += v * v;
        }
        #pragma unroll
        for (int o = 16; o; o >>= 1) ss += __shfl_xor_sync(0xFFFFFFFFu, ss, o);
        if (lane == 0) sred[t >> 5] = ss;
        __syncthreads();
        if (t == 0) {
            float tot = 0.f;
            #pragma unroll
            for (int w = 0; w < THREADS / 32; ++w) tot += sred[w];
            sc[k] = -scl * rsqrtf(fmaxf(tot, EPS));
        }

        // ---- 3 register stages (bits 8..10 of n == bits of q) ----
        #pragma unroll
        for (int B = 1; B < 8; B <<= 1) {
            #pragma unroll
            for (int q = 0; q < 8; ++q) {
                if (!(q & B)) {
                    float a0 = res[k][q], a1 = res[k][q | B];
                    res[k][q]     = a0 + a1;
                    res[k][q | B] = a0 - a1;
                }
            }
        }

        // ---- 5 shuffle stages (bits 0..4 of n == lane bits of t) ----
        #pragma unroll
        for (int h = 1; h <= 16; h <<= 1) {
            #pragma unroll
            for (int q = 0; q < 8; ++q) {
                float o = __shfl_xor_sync(0xFFFFFFFFu, res[k][q], h);
                res[k][q] = (t & h) ? (o - res[k][q]) : (res[k][q] + o);
            }
        }

        // ---- 3 smem exchange stages (bits 5..7 of n == warp bits of t) ----
        #pragma unroll
        for (int h = 32; h <= 128; h <<= 1) {
            __syncthreads();                       // buffer free from previous use
            #pragma unroll
            for (int q = 0; q < 8; ++q) xch[q][t] = res[k][q];
            __syncthreads();
            #pragma unroll
            for (int q = 0; q < 8; ++q) {
                float o = xch[q][t ^ h];
                res[k][q] = (t & h) ? (o - res[k][q]) : (res[k][q] + o);
            }
        }
    }

    __syncthreads();
    const float c0 = sc[0], c1 = sc[1], c2 = sc[2], c3 = sc[3];

    float* __restrict__ o0 = out + (size_t)b * OUT_DIM;
    float* __restrict__ o1 = out + (size_t)(b +     rowstride) * OUT_DIM;
    float* __restrict__ o2 = out + (size_t)(b + 2 * rowstride) * OUT_DIM;
    float* __restrict__ o3 = out + (size_t)(b + 3 * rowstride) * OUT_DIM;

    // ---- epilogue: out[row, j] = c_row * y[j & 2047] + bias[j]
    // j = t + 256*m  =>  y[j & 2047] = res[row][m & 7]  (no smem reads!)
    #pragma unroll 1
    for (int m0 = 0; m0 <= 56; m0 += 8) {
        #pragma unroll
        for (int u = 0; u < 8; ++u) {
            int j = t + ((m0 + u) << 8);
            if (j < OUT_DIM) {
                float bv = __ldg(bias + j);
                o0[j] = fmaf(c0, res[0][u], bv);
                o1[j] = fmaf(c1, res[1][u], bv);
                o2[j] = fmaf(c2, res[2][u], bv);
                o3[j] = fmaf(c3, res[3][u], bv);
            }
        }
    }
}

extern "C" void kernel_launch(void* const* d_in, const int* in_sizes, int n_in,
                              void* d_out, int out_size)
{
    const float* x     = (const float*)d_in[0];
    const float* scale = (const float*)d_in[1];
    const float* bias  = (const float*)d_in[2];
    float* out = (float*)d_out;

    const int batch = in_sizes[0] / IN_DIM;     // 4096
    const int rowstride = batch / R;            // 1024
    hc_kernel<<<rowstride, THREADS>>>(x, scale, bias, out, rowstride);
}

// round 3
// speedup vs baseline: 1.4355x; 1.4355x over previous
#include <cuda_runtime.h>

#define IN_DIM   2048
#define OUT_DIM  14951
#define THREADS  256
#define EPS      1e-12f

__global__ __launch_bounds__(THREADS)
void hc_kernel(const float* __restrict__ x,
               const float* __restrict__ scale,
               const float* __restrict__ bias,
               float* __restrict__ out)
{
    __shared__ float xch[8][THREADS];      // 8 KB exchange buffer (conflict-free)
    __shared__ float sred[THREADS / 32];
    __shared__ float sc;

    const int t    = threadIdx.x;
    const int row  = blockIdx.x;
    const int lane = t & 31;

    // res[q] holds element n = q*256 + t of this row's (partial) transform
    float res[8];

    const float* __restrict__ xr = x + (size_t)row * IN_DIM;

    // ---- load (coalesced) + sum of squares ----
    float ss = 0.f;
#pragma unroll
    for (int q = 0; q < 8; ++q) {
        float v = xr[q * THREADS + t];
        res[q] = v;
        ss += v * v;
    }
#pragma unroll
    for (int o = 16; o; o >>= 1) ss += __shfl_xor_sync(0xFFFFFFFFu, ss, o);
    if (lane == 0) sred[t >> 5] = ss;
    __syncthreads();
    if (t == 0) {
        float tot = 0.f;
#pragma unroll
        for (int w = 0; w < THREADS / 32; ++w) tot += sred[w];
        sc = -scale[0] * rsqrtf(fmaxf(tot, EPS));
    }

    // ---- 3 register stages (bits 8..10 of n == bits of q) ----
#pragma unroll
    for (int B = 1; B < 8; B <<= 1) {
#pragma unroll
        for (int q = 0; q < 8; ++q) {
            if (!(q & B)) {
                float a0 = res[q], a1 = res[q | B];
                res[q]     = a0 + a1;
                res[q | B] = a0 - a1;
            }
        }
    }

    // ---- 5 shuffle stages (bits 0..4 of n == lane bits of t) ----
#pragma unroll
    for (int h = 1; h <= 16; h <<= 1) {
#pragma unroll
        for (int q = 0; q < 8; ++q) {
            float o = __shfl_xor_sync(0xFFFFFFFFu, res[q], h);
            res[q] = (t & h) ? (o - res[q]) : (res[q] + o);
        }
    }

    // ---- 3 smem exchange stages (bits 5..7 of n == warp bits of t) ----
#pragma unroll
    for (int h = 32; h <= 128; h <<= 1) {
        __syncthreads();
#pragma unroll
        for (int q = 0; q < 8; ++q) xch[q][t] = res[q];
        __syncthreads();
#pragma unroll
        for (int q = 0; q < 8; ++q) {
            float o = xch[q][t ^ h];
            res[q] = (t & h) ? (o - res[q]) : (res[q] + o);
        }
    }

    __syncthreads();
    const float c = sc;
    float* __restrict__ orow = out + (size_t)row * OUT_DIM;

    // ---- epilogue: out[row, j] = c * y[j & 2047] + bias[j]
    // j = t + 256*m  =>  y[j & 2047] = res[m & 7]   (no smem reads)
#pragma unroll
    for (int m0 = 0; m0 < 64; m0 += 8) {
#pragma unroll
        for (int u = 0; u < 8; ++u) {
            int j = t + ((m0 + u) << 8);
            if (j < OUT_DIM) {
                orow[j] = fmaf(c, res[u], __ldg(bias + j));
            }
        }
    }
}

extern "C" void kernel_launch(void* const* d_in, const int* in_sizes, int n_in,
                              void* d_out, int out_size)
{
    const float* x     = (const float*)d_in[0];
    const float* scale = (const float*)d_in[1];
    const float* bias  = (const float*)d_in[2];
    float* out = (float*)d_out;

    const int batch = in_sizes[0] / IN_DIM;     // 4096
    hc_kernel<<<batch, THREADS>>>(x, scale, bias, out);
}